// round 16
// baseline (speedup 1.0000x reference)
#include <cuda_runtime.h>
#include <cuda_bf16.h>
#include <math.h>
#include <stdint.h>

#define E_DIM 1024
#define QLEN  1024
#define BATCH 4
#define NH    16
#define DH    64

#define SB2 36   // bf16 smem row stride (32 data words + 2 aux + 2 pad)
#define SS 68    // S stride (f32)

// attn smem word offsets
#define OQ2 0        // q2 bf16: 64 x 36
#define OKB 2304     // k bf16: 64 x 36
#define ORP 4608     // rp bf16: 128 x 36
#define OV  9216     // v bf16: 64 x 36 = 2304
#define OS  11520    // S f32: 64 x 68 = 4352
#define OP  15872    // P bf16 packed: 64 x 36 = 2304
#define OM  18176    // m/l/c: 192
#define AW  18368    // total words = 73472 B

// ---------------- scratch (device globals; no allocation allowed) ----------------
__device__ __nv_bfloat16 g_qb[BATCH * NH * QLEN * DH];   // q, bf16
__device__ __nv_bfloat16 g_kb[BATCH * NH * QLEN * DH];   // k/32, bf16
__device__ __nv_bfloat16 g_vb[BATCH * NH * QLEN * DH];   // v, bf16
__device__ __nv_bfloat16 g_rpb[NH * QLEN * DH];          // rp/32, bf16
__device__ uint32_t g_ckb[BATCH * NH * QLEN];            // packed (bf16(ck/32), 0)
__device__ uint32_t g_crb[NH * QLEN];                    // packed (bf16(cr/32), 0)
__device__ float g_attn[BATCH * QLEN * E_DIM];
__device__ float g_o[BATCH * QLEN * E_DIM];
__device__ float g_wt[5 * E_DIM * E_DIM];                // transposed tf32 weights

// ================= helpers =================
__device__ __forceinline__ float tf32r(float x) {
    asm("cvt.rna.tf32.f32 %0, %1;" : "=f"(x) : "f"(x));
    return x;
}
__device__ __forceinline__ uint32_t bf2pack(float e, float o) {
    uint32_t u;
    asm("cvt.rn.bf16x2.f32 %0, %1, %2;" : "=r"(u) : "f"(o), "f"(e));
    return u;
}

#define MMA8(d, a0, a1, a2, a3, b0, b1) \
    asm volatile("mma.sync.aligned.m16n8k8.row.col.f32.tf32.tf32.f32 " \
        "{%0,%1,%2,%3}, {%4,%5,%6,%7}, {%8,%9}, {%0,%1,%2,%3};" \
        : "+f"((d)[0]), "+f"((d)[1]), "+f"((d)[2]), "+f"((d)[3]) \
        : "r"(a0), "r"(a1), "r"(a2), "r"(a3), "r"(b0), "r"(b1))

#define MMA16B(d, a0, a1, a2, a3, b0, b1) \
    asm volatile("mma.sync.aligned.m16n8k16.row.col.f32.bf16.bf16.f32 " \
        "{%0,%1,%2,%3}, {%4,%5,%6,%7}, {%8,%9}, {%0,%1,%2,%3};" \
        : "+f"((d)[0]), "+f"((d)[1]), "+f"((d)[2]), "+f"((d)[3]) \
        : "r"(a0), "r"(a1), "r"(a2), "r"(a3), "r"(b0), "r"(b1))

#define MMA8B(d, a0, a1, b0) \
    asm volatile("mma.sync.aligned.m16n8k8.row.col.f32.bf16.bf16.f32 " \
        "{%0,%1,%2,%3}, {%4,%5}, {%6}, {%0,%1,%2,%3};" \
        : "+f"((d)[0]), "+f"((d)[1]), "+f"((d)[2]), "+f"((d)[3]) \
        : "r"(a0), "r"(a1), "r"(b0))

#define LDSM4T(r0, r1, r2, r3, addr) \
    asm volatile("ldmatrix.sync.aligned.m8n8.x4.trans.shared.b16 {%0,%1,%2,%3}, [%4];" \
        : "=r"(r0), "=r"(r1), "=r"(r2), "=r"(r3) : "r"(addr))

#define CP16(saddr, gptr) \
    asm volatile("cp.async.cg.shared.global [%0], [%1], 16;" :: "r"(saddr), "l"(gptr) : "memory")
#define CP16Z(saddr, gptr, sz) \
    asm volatile("cp.async.cg.shared.global [%0], [%1], 16, %2;" :: "r"(saddr), "l"(gptr), "r"(sz) : "memory")
#define CP4(saddr, gptr) \
    asm volatile("cp.async.ca.shared.global [%0], [%1], 4;" :: "r"(saddr), "l"(gptr) : "memory")
#define CP4Z(saddr, gptr, sz) \
    asm volatile("cp.async.ca.shared.global [%0], [%1], 4, %2;" :: "r"(saddr), "l"(gptr), "r"(sz) : "memory")
#define CPCOMMIT() asm volatile("cp.async.commit_group;" ::: "memory")
#define CPWAIT2()  asm volatile("cp.async.wait_group 2;" ::: "memory")
#define CPWAIT0()  asm volatile("cp.async.wait_group 0;" ::: "memory")

// ---------------- weight transpose + tf32 round: 5 x 1024x1024 ----------------
__global__ void __launch_bounds__(256) transpose5(const float* __restrict__ a0,
                                                  const float* __restrict__ a1,
                                                  const float* __restrict__ a2,
                                                  const float* __restrict__ a3,
                                                  const float* __restrict__ a4)
{
    __shared__ float t[32][33];
    const float* src = (blockIdx.z == 0) ? a0 : (blockIdx.z == 1) ? a1 :
                       (blockIdx.z == 2) ? a2 : (blockIdx.z == 3) ? a3 : a4;
    float* dst = g_wt + (size_t)blockIdx.z * E_DIM * E_DIM;
    int x = blockIdx.x * 32 + threadIdx.x;
    int y0 = blockIdx.y * 32 + threadIdx.y;
#pragma unroll
    for (int j = 0; j < 4; j++)
        t[threadIdx.y + 8 * j][threadIdx.x] = src[(size_t)(y0 + 8 * j) * E_DIM + x];
    __syncthreads();
    int x2 = blockIdx.y * 32 + threadIdx.x;
    int y2 = blockIdx.x * 32 + threadIdx.y;
#pragma unroll
    for (int j = 0; j < 4; j++)
        dst[(size_t)(y2 + 8 * j) * E_DIM + x2] = tf32r(t[threadIdx.x][threadIdx.y + 8 * j]);
}

// ---------------- tf32 GEMM body, 256 threads = 8 warps (2m x 4n), warp 64x32 ----------------
// cp.async 4-stage. out modes: 0 bf16 head-major (batch), 2 bf16 head-major (no batch),
//                              3 f32 row-major
__device__ __forceinline__ void gemm_body(const float* __restrict__ A,
                                          const float* __restrict__ Bt,
                                          void* __restrict__ C,
                                          int mode, float scale, int m0, int n0,
                                          uint32_t* sA, uint32_t* sB)
{
    const int tid = threadIdx.x;
    const int wid = tid >> 5, lane = tid & 31;
    const int mw = wid >> 2, nw = wid & 3;
    const int g = lane >> 2, tt = lane & 3;
    const int swz = (g & 6) << 1;
    const int c0w = tt + (0 ^ swz);
    const int c1w = tt + (4 ^ swz);
    const int baseA = (mw * 64 + g) * 16;
    const int baseB = (nw * 32 + g) * 16;

    const int q4 = tid & 3;
    const int row0 = tid >> 2;          // 0..63
    int f_w[2];
#pragma unroll
    for (int l = 0; l < 2; l++) {
        int row = row0 + 64 * l;
        f_w[l] = row * 16 + ((4 * q4) ^ ((row & 6) << 1));
    }

    const float* Ap = A + (size_t)(m0 + row0) * E_DIM + 4 * q4;
    const float* Bp = Bt + (size_t)(n0 + row0) * E_DIM + 4 * q4;
    const uint32_t aBase = (uint32_t)__cvta_generic_to_shared(sA);
    const uint32_t bBase = (uint32_t)__cvta_generic_to_shared(sB);

    float d[4][4][4];
#pragma unroll
    for (int i = 0; i < 4; i++)
#pragma unroll
        for (int j = 0; j < 4; j++)
#pragma unroll
            for (int e = 0; e < 4; e++) d[i][j][e] = 0.f;

#define ISSUE_CHUNK(c, st) do { \
    _Pragma("unroll") \
    for (int l = 0; l < 2; l++) { \
        CP16(aBase + (st) * 8192 + f_w[l] * 4, Ap + (size_t)(64 * l) * E_DIM + (c) * 16); \
        CP16(bBase + (st) * 8192 + f_w[l] * 4, Bp + (size_t)(64 * l) * E_DIM + (c) * 16); \
    } \
    CPCOMMIT(); \
} while (0)

    ISSUE_CHUNK(0, 0);
    ISSUE_CHUNK(1, 1);
    ISSUE_CHUNK(2, 2);

    for (int c = 0; c < 64; c++) {
        const int st = c & 3;
        CPWAIT2();
        __syncthreads();
#pragma unroll
        for (int ks = 0; ks < 2; ks++) {
            const int ko = ks << 3;
            uint32_t af[4][4];
            uint32_t bf2[4][2];
#pragma unroll
            for (int ma = 0; ma < 4; ma++) {
                af[ma][0] = sA[st * 2048 + baseA + ma * 256 +       (c0w ^ ko)];
                af[ma][1] = sA[st * 2048 + baseA + ma * 256 + 128 + (c0w ^ ko)];
                af[ma][2] = sA[st * 2048 + baseA + ma * 256 +       (c1w ^ ko)];
                af[ma][3] = sA[st * 2048 + baseA + ma * 256 + 128 + (c1w ^ ko)];
            }
#pragma unroll
            for (int nb = 0; nb < 4; nb++) {
                bf2[nb][0] = sB[st * 2048 + baseB + nb * 128 + (c0w ^ ko)];
                bf2[nb][1] = sB[st * 2048 + baseB + nb * 128 + (c1w ^ ko)];
            }
#pragma unroll
            for (int ma = 0; ma < 4; ma++)
#pragma unroll
                for (int nb = 0; nb < 4; nb++)
                    MMA8(d[ma][nb], af[ma][0], af[ma][1], af[ma][2], af[ma][3],
                         bf2[nb][0], bf2[nb][1]);
        }
        if (c < 61) ISSUE_CHUNK(c + 3, (c + 3) & 3);
    }
#undef ISSUE_CHUNK

#pragma unroll
    for (int ma = 0; ma < 4; ma++) {
        const int m_base = m0 + mw * 64 + ma * 16 + g;
#pragma unroll
        for (int nb = 0; nb < 4; nb++) {
            const int n = n0 + nw * 32 + nb * 8 + tt * 2;
#pragma unroll
            for (int half = 0; half < 2; half++) {
                const int m = m_base + half * 8;
                float vx = d[ma][nb][half * 2], vy = d[ma][nb][half * 2 + 1];
                if (mode == 0) {
                    int b = m >> 10, i = m & 1023, hh = n >> 6, dd = n & 63;
                    ((uint32_t*)C)[((((size_t)b * NH + hh) * QLEN + i) * DH + dd) >> 1] =
                        bf2pack(vx * scale, vy * scale);
                } else if (mode == 2) {
                    int hh = n >> 6, dd = n & 63;
                    ((uint32_t*)C)[(((size_t)hh * QLEN + m) * DH + dd) >> 1] =
                        bf2pack(vx * scale, vy * scale);
                } else {
                    *(float2*)&((float*)C)[(size_t)m * E_DIM + n] = make_float2(vx, vy);
                }
            }
        }
    }
}

__global__ void __launch_bounds__(256, 2) gemm_proj(const float* __restrict__ w,
                                                    const float* __restrict__ r)
{
    __shared__ uint32_t sA[4][2048];
    __shared__ uint32_t sB[4][2048];
    const int z = blockIdx.z;
    if (z == 3 && blockIdx.y >= 8) return;
    const size_t WSZ = (size_t)E_DIM * E_DIM;
    const float* A = (z == 3) ? r : w;
    const float* Bt = g_wt + (size_t)z * WSZ;
    void* C = (z == 0) ? (void*)g_qb : (z == 1) ? (void*)g_kb :
              (z == 2) ? (void*)g_vb : (void*)g_rpb;
    int mode = (z == 3) ? 2 : 0;
    float scale = (z == 1 || z == 3) ? 0.03125f : 1.0f;
    gemm_body(A, Bt, C, mode, scale, blockIdx.y * 128, blockIdx.x * 128,
              &sA[0][0], &sB[0][0]);
}

__global__ void __launch_bounds__(256, 2) gemm_wo(const float* __restrict__ A,
                                                  const float* __restrict__ Bt,
                                                  float* __restrict__ C)
{
    __shared__ uint32_t sA[4][2048];
    __shared__ uint32_t sB[4][2048];
    gemm_body(A, Bt, C, 3, 1.0f, blockIdx.y * 128, blockIdx.x * 128,
              &sA[0][0], &sB[0][0]);
}

// ---------------- ck/cr from bf16 k/32, rp/32 ----------------
__global__ void __launch_bounds__(256) ckcr_kernel(const float* __restrict__ rwb,
                                                   const float* __restrict__ rrb)
{
    int gw = (blockIdx.x * blockDim.x + threadIdx.x) >> 5;
    int lane = threadIdx.x & 31;
    const int NCK = BATCH * NH * QLEN;
    float s;
    if (gw < NCK) {
        int h = (gw >> 10) & (NH - 1);
        uint32_t u = ((const uint32_t*)g_kb)[(size_t)gw * 32 + lane];
        float lo = __uint_as_float(u << 16);
        float hi = __uint_as_float(u & 0xFFFF0000u);
        s = lo * rwb[h * DH + 2 * lane] + hi * rwb[h * DH + 2 * lane + 1];
    } else {
        int w2 = gw - NCK;
        if (w2 >= NH * QLEN) return;
        int h = w2 >> 10;
        uint32_t u = ((const uint32_t*)g_rpb)[(size_t)w2 * 32 + lane];
        float lo = __uint_as_float(u << 16);
        float hi = __uint_as_float(u & 0xFFFF0000u);
        s = lo * rrb[h * DH + 2 * lane] + hi * rrb[h * DH + 2 * lane + 1];
    }
#pragma unroll
    for (int off = 16; off; off >>= 1) s += __shfl_down_sync(0xffffffffu, s, off);
    if (lane == 0) {
        if (gw < NCK) g_ckb[gw] = bf2pack(s, 0.f);
        else g_crb[gw - NCK] = bf2pack(s, 0.f);
    }
}

// ---------------- fused attention: full-bf16 MMAs, windowed P, rolling rp, cp.async ----------------
__global__ void __launch_bounds__(256, 3) attn_mma()
{
    extern __shared__ float sm[];
    uint32_t* smu = (uint32_t*)sm;
    float* S_s = sm + OS;
    float* m_s = sm + OM;
    float* l_s = sm + OM + 64;
    float* c_s = sm + OM + 128;

    const int tid = threadIdx.x;
    const int wid = tid >> 5, lane = tid & 31;
    const int g = lane >> 2, tg = lane & 3;
    const int qt = 15 - blockIdx.x;
    const int h = blockIdx.y, b = blockIdx.z;
    const int i0 = qt * 64;
    const size_t headelem = ((size_t)b * NH + h) * QLEN * DH;
    const char* qb_p  = (const char*)g_qb  + (headelem + (size_t)i0 * DH) * 2;
    const char* kb_p  = (const char*)g_kb  + headelem * 2;
    const char* vb_p  = (const char*)g_vb  + headelem * 2;
    const char* rp_p  = (const char*)g_rpb + (size_t)h * QLEN * DH * 2;
    const uint32_t* ckb_p = g_ckb + ((size_t)b * NH + h) * QLEN;
    const uint32_t* crb_p = g_crb + (size_t)h * QLEN;

    const int mt = wid >> 1;
    const int nt = wid & 1;
    const int u0 = 48 - 16 * mt;
    const int pcol0 = u0 + nt * 40;

    const uint32_t q2S = (uint32_t)__cvta_generic_to_shared(smu + OQ2);
    const uint32_t kS  = (uint32_t)__cvta_generic_to_shared(smu + OKB);
    const uint32_t rpS = (uint32_t)__cvta_generic_to_shared(smu + ORP);
    const uint32_t vS  = (uint32_t)__cvta_generic_to_shared(smu + OV);

    // ---- static init: aux/pad words ----
    if (tid < 64) {
        int ba = OQ2 + tid * SB2;
        smu[ba + 32] = 0x00003F80u;  // (bf16 1.0, 0) -> A' aux = [1,0,...]
        smu[ba + 33] = 0; smu[ba + 34] = 0; smu[ba + 35] = 0;
        ba = OKB + tid * SB2;
        smu[ba + 33] = 0; smu[ba + 34] = 0; smu[ba + 35] = 0;
        m_s[tid] = -INFINITY; l_s[tid] = 0.f;
    }
    if (tid < 128) {
        int ba = ORP + tid * SB2;
        smu[ba + 33] = 0; smu[ba + 34] = 0; smu[ba + 35] = 0;
    }

    // ---- prologue fills (q2 + kt=0 k/v/rp/aux) ----
    {
        const int m_base0 = 960 - i0;
#pragma unroll
        for (int it = 0; it < 2; it++) {   // q2 + k + v: 64 rows x 8 granules each
            int idx = tid + 256 * it;
            int row = idx >> 3, j = idx & 7;
            CP16(q2S + (uint32_t)(row * SB2 + 4 * j) * 4, qb_p + (size_t)row * 128 + 16 * j);
            CP16(kS  + (uint32_t)(row * SB2 + 4 * j) * 4, kb_p + (size_t)row * 128 + 16 * j);
            CP16(vS  + (uint32_t)(row * SB2 + 4 * j) * 4, vb_p + (size_t)row * 128 + 16 * j);
        }
#pragma unroll
        for (int it = 0; it < 4; it++) {   // rp: 128 rows x 8 granules
            int idx = tid + 256 * it;
            int row = idx >> 3, j = idx & 7;
            int mg = m_base0 + row;
            int slot = mg & 127;
            uint32_t sz = (mg < QLEN) ? 16u : 0u;
            int mgc = (mg < QLEN) ? mg : (QLEN - 1);
            CP16Z(rpS + (uint32_t)(slot * SB2 + 4 * j) * 4, rp_p + (size_t)mgc * 128 + 16 * j, sz);
        }
        if (tid < 64) {
            CP4(kS + (uint32_t)(tid * SB2 + 32) * 4, ckb_p + tid);
        } else if (tid < 192) {
            int row = tid - 64;
            int mg = m_base0 + row;
            int slot = mg & 127;
            uint32_t sz = (mg < QLEN) ? 4u : 0u;
            int mgc = (mg < QLEN) ? mg : (QLEN - 1);
            CP4Z(rpS + (uint32_t)(slot * SB2 + 32) * 4, crb_p + mgc, sz);
        }
        CPCOMMIT();
    }

    float acc_o[4][4];
#pragma unroll
    for (int na = 0; na < 4; na++)
#pragma unroll
        for (int e = 0; e < 4; e++) acc_o[na][e] = 0.f;

    const int aR0 = OQ2 + (mt * 16 + g) * SB2;
    const int aR1 = aR0 + 8 * SB2;
    const int aP0 = OP + (mt * 16 + g) * SB2;
    const int aP1 = aP0 + 8 * SB2;
    // ldmatrix base for V (per-lane): matrix row j = lane&15, col half = (lane>>4)*8
    const uint32_t vmBase = vS +
        (uint32_t)(((lane & 15) * SB2 + ((nt * 32 + ((lane >> 4) << 3)) >> 1)) * 4);

    for (int kt = 0; kt <= qt; kt++) {
        const int j0 = kt * 64;
        const int m_base = 960 - i0 + j0;
        const int mb7 = m_base & 127;

        CPWAIT0();
        __syncthreads();

        int kb[4], pb[5];
#pragma unroll
        for (int na = 0; na < 4; na++) kb[na] = OKB + (nt * 32 + na * 8 + g) * SB2;
#pragma unroll
        for (int na = 0; na < 5; na++)
            pb[na] = ORP + ((mb7 + pcol0 + na * 8 + g) & 127) * SB2;

        // ---- S-phase: bf16 k16 MMAs ----
        float sc[4][4], pc[5][4];
#pragma unroll
        for (int na = 0; na < 4; na++)
#pragma unroll
            for (int e = 0; e < 4; e++) sc[na][e] = 0.f;
#pragma unroll
        for (int na = 0; na < 5; na++)
#pragma unroll
            for (int e = 0; e < 4; e++) pc[na][e] = 0.f;
#pragma unroll
        for (int s = 0; s < 4; s++) {
            uint32_t a0 = smu[aR0 + 8 * s + tg];
            uint32_t a1 = smu[aR1 + 8 * s + tg];
            uint32_t a2 = smu[aR0 + 8 * s + 4 + tg];
            uint32_t a3 = smu[aR1 + 8 * s + 4 + tg];
#pragma unroll
            for (int na = 0; na < 4; na++)
                MMA16B(sc[na], a0, a1, a2, a3,
                       smu[kb[na] + 8 * s + tg], smu[kb[na] + 8 * s + 4 + tg]);
#pragma unroll
            for (int na = 0; na < 5; na++)
                MMA16B(pc[na], a0, a1, a2, a3,
                       smu[pb[na] + 8 * s + tg], smu[pb[na] + 8 * s + 4 + tg]);
        }
        {   // aux k8 (bias via [1] column)
            uint32_t a0 = smu[aR0 + 32 + tg];
            uint32_t a1 = smu[aR1 + 32 + tg];
#pragma unroll
            for (int na = 0; na < 4; na++)
                MMA8B(sc[na], a0, a1, smu[kb[na] + 32 + tg]);
#pragma unroll
            for (int na = 0; na < 5; na++)
                MMA8B(pc[na], a0, a1, smu[pb[na] + 32 + tg]);
        }
        // scatter P window (assign into S band)
#pragma unroll
        for (int na = 0; na < 5; na++) {
            int ub = pcol0 + na * 8 + 2 * tg;
#pragma unroll
            for (int e = 0; e < 4; e++) {
                int il = mt * 16 + g + (e >> 1) * 8;
                int jl = ub + (e & 1) - 63 + il;
                if (jl >= 0 && jl < 64) S_s[il * SS + jl] = pc[na][e];
            }
        }
        __syncthreads();

        // ---- early issue of k/rp/aux for kt+1 ----
        if (kt < qt) {
            const int j1 = j0 + 64;
            const int mb1 = m_base + 64;
#pragma unroll
            for (int it = 0; it < 2; it++) {   // k: 64 rows x 8 granules
                int idx = tid + 256 * it;
                int row = idx >> 3, j = idx & 7;
                CP16(kS + (uint32_t)(row * SB2 + 4 * j) * 4,
                     kb_p + (size_t)(j1 + row) * 128 + 16 * j);
            }
#pragma unroll
            for (int it = 0; it < 2; it++) {   // rp top 64 rows x 8 granules
                int idx = tid + 256 * it;
                int row = 64 + (idx >> 3), j = idx & 7;
                int mg = mb1 + row;
                int slot = mg & 127;
                uint32_t sz = (mg < QLEN) ? 16u : 0u;
                int mgc = (mg < QLEN) ? mg : (QLEN - 1);
                CP16Z(rpS + (uint32_t)(slot * SB2 + 4 * j) * 4,
                      rp_p + (size_t)mgc * 128 + 16 * j, sz);
            }
            if (tid < 64) {
                CP4(kS + (uint32_t)(tid * SB2 + 32) * 4, ckb_p + j1 + tid);
            } else if (tid < 128) {
                int row = tid;   // 64..127
                int mg = mb1 + row;
                int slot = mg & 127;
                uint32_t sz = (mg < QLEN) ? 4u : 0u;
                int mgc = (mg < QLEN) ? mg : (QLEN - 1);
                CP4Z(rpS + (uint32_t)(slot * SB2 + 32) * 4, crb_p + mgc, sz);
            }
        }

        // ---- S1 accumulate into S (float2 RMW) ----
#pragma unroll
        for (int na = 0; na < 4; na++) {
            int cb = nt * 32 + na * 8 + 2 * tg;
            int il0 = mt * 16 + g;
            float2 x0 = *(float2*)&S_s[il0 * SS + cb];
            x0.x += sc[na][0]; x0.y += sc[na][1];
            *(float2*)&S_s[il0 * SS + cb] = x0;
            float2 x1 = *(float2*)&S_s[(il0 + 8) * SS + cb];
            x1.x += sc[na][2]; x1.y += sc[na][3];
            *(float2*)&S_s[(il0 + 8) * SS + cb] = x1;
        }
        __syncthreads();

        // ---- online softmax: reads f32 S, writes packed bf16 P ----
        {
            int row = tid >> 2, p = tid & 3;
            int c0 = p * 16;
            bool diag = (kt == qt);
            float mo = m_s[row];
            float mx = mo;
            float4 vv[4];
#pragma unroll
            for (int jv = 0; jv < 4; jv++) {
                vv[jv] = *(const float4*)&S_s[row * SS + c0 + jv * 4];
                if (diag) {
                    int base = c0 + jv * 4;
                    if (base + 0 > row) vv[jv].x = -1e30f;
                    if (base + 1 > row) vv[jv].y = -1e30f;
                    if (base + 2 > row) vv[jv].z = -1e30f;
                    if (base + 3 > row) vv[jv].w = -1e30f;
                }
                mx = fmaxf(mx, fmaxf(fmaxf(vv[jv].x, vv[jv].y), fmaxf(vv[jv].z, vv[jv].w)));
            }
            mx = fmaxf(mx, __shfl_xor_sync(0xffffffffu, mx, 1));
            mx = fmaxf(mx, __shfl_xor_sync(0xffffffffu, mx, 2));
            float corr = __expf(mo - mx);
            float sum = 0.f;
            int pr = OP + row * SB2 + p * 8;
#pragma unroll
            for (int jv = 0; jv < 4; jv++) {
                float4 pv;
                pv.x = __expf(vv[jv].x - mx);
                pv.y = __expf(vv[jv].y - mx);
                pv.z = __expf(vv[jv].z - mx);
                pv.w = __expf(vv[jv].w - mx);
                sum += (pv.x + pv.y) + (pv.z + pv.w);
                uint2 u;
                u.x = bf2pack(pv.x, pv.y);
                u.y = bf2pack(pv.z, pv.w);
                *(uint2*)&smu[pr + 2 * jv] = u;
            }
            sum += __shfl_xor_sync(0xffffffffu, sum, 1);
            sum += __shfl_xor_sync(0xffffffffu, sum, 2);
            if (p == 0) {
                m_s[row] = mx;
                l_s[row] = l_s[row] * corr + sum;
                c_s[row] = corr;
            }
        }
        __syncthreads();

        // ---- PV (bf16, ldmatrix.trans for V) ----
        {
            float cr0 = c_s[mt * 16 + g], cr1 = c_s[mt * 16 + 8 + g];
#pragma unroll
            for (int na = 0; na < 4; na++) {
                acc_o[na][0] *= cr0; acc_o[na][1] *= cr0;
                acc_o[na][2] *= cr1; acc_o[na][3] *= cr1;
            }
#pragma unroll
            for (int ks = 0; ks < 4; ks++) {
                uint32_t a0 = smu[aP0 + 8 * ks + tg];
                uint32_t a1 = smu[aP1 + 8 * ks + tg];
                uint32_t a2 = smu[aP0 + 8 * ks + 4 + tg];
                uint32_t a3 = smu[aP1 + 8 * ks + 4 + tg];
#pragma unroll
                for (int nb16 = 0; nb16 < 2; nb16++) {
                    uint32_t r0, r1, r2, r3;
                    LDSM4T(r0, r1, r2, r3,
                           vmBase + (uint32_t)((16 * ks * SB2 + 8 * nb16) * 4));
                    MMA16B(acc_o[2 * nb16 + 0], a0, a1, a2, a3, r0, r1);
                    MMA16B(acc_o[2 * nb16 + 1], a0, a1, a2, a3, r2, r3);
                }
            }
        }
        __syncthreads();

        // ---- early issue of v for kt+1, then commit ----
        if (kt < qt) {
            const int j1 = j0 + 64;
#pragma unroll
            for (int it = 0; it < 2; it++) {
                int idx = tid + 256 * it;
                int row = idx >> 3, j = idx & 7;
                CP16(vS + (uint32_t)(row * SB2 + 4 * j) * 4,
                     vb_p + (size_t)(j1 + row) * 128 + 16 * j);
            }
        }
        CPCOMMIT();
    }

    // ---- write out (token-major for Wo GEMM) ----
    {
        int il0 = mt * 16 + g;
        float inv0 = 1.f / l_s[il0], inv1 = 1.f / l_s[il0 + 8];
#pragma unroll
        for (int na = 0; na < 4; na++) {
            int d0 = h * DH + nt * 32 + na * 8 + 2 * tg;
            size_t o0 = ((size_t)b * QLEN + i0 + il0) * E_DIM + d0;
            size_t o1 = ((size_t)b * QLEN + i0 + il0 + 8) * E_DIM + d0;
            *(float2*)&g_attn[o0] = make_float2(acc_o[na][0] * inv0, acc_o[na][1] * inv0);
            *(float2*)&g_attn[o1] = make_float2(acc_o[na][2] * inv1, acc_o[na][3] * inv1);
        }
    }
}

// ---------------- residual + layernorm (float4) ----------------
__global__ void __launch_bounds__(256) addln_kernel(const float* __restrict__ w,
                                                    const float* __restrict__ gamma,
                                                    const float* __restrict__ beta,
                                                    float* __restrict__ out)
{
    __shared__ float xs[E_DIM];
    __shared__ float red[64];
    int row = blockIdx.x;
    size_t base = (size_t)row * E_DIM;
    int j = threadIdx.x * 4;
    float4 a = *(const float4*)&w[base + j];
    float4 o = *(const float4*)&g_o[base + j];
    float4 x = make_float4(a.x + o.x, a.y + o.y, a.z + o.z, a.w + o.w);
    *(float4*)&xs[j] = x;
    float s = (x.x + x.y) + (x.z + x.w);
    float s2 = (x.x * x.x + x.y * x.y) + (x.z * x.z + x.w * x.w);
#pragma unroll
    for (int off = 16; off; off >>= 1) {
        s  += __shfl_down_sync(0xffffffffu, s, off);
        s2 += __shfl_down_sync(0xffffffffu, s2, off);
    }
    int wid = threadIdx.x >> 5, lane = threadIdx.x & 31;
    if (lane == 0) { red[wid] = s; red[32 + wid] = s2; }
    __syncthreads();
    if (threadIdx.x == 0) {
        float S = 0.f, S2 = 0.f;
        for (int i = 0; i < 8; i++) { S += red[i]; S2 += red[32 + i]; }
        red[0] = S; red[1] = S2;
    }
    __syncthreads();
    float mean = red[0] * (1.f / E_DIM);
    float var = red[1] * (1.f / E_DIM) - mean * mean;
    float inv = rsqrtf(var + 1e-3f);
    float4 gm = *(const float4*)&gamma[j];
    float4 bt = *(const float4*)&beta[j];
    float4 xv = *(const float4*)&xs[j];
    float4 r;
    r.x = (xv.x - mean) * inv * gm.x + bt.x;
    r.y = (xv.y - mean) * inv * gm.y + bt.y;
    r.z = (xv.z - mean) * inv * gm.z + bt.z;
    r.w = (xv.w - mean) * inv * gm.w + bt.w;
    *(float4*)&out[base + j] = r;
}

// ---------------- launch ----------------
extern "C" void kernel_launch(void* const* d_in, const int* in_sizes, int n_in,
                              void* d_out, int out_size)
{
    const float* w     = (const float*)d_in[0];
    const float* r     = (const float*)d_in[1];
    const float* rwb   = (const float*)d_in[2];
    const float* rrb   = (const float*)d_in[3];
    // d_in[4] attn_mask: strictly-causal, computed analytically
    const float* Wq    = (const float*)d_in[5];
    const float* Wk    = (const float*)d_in[6];
    const float* Wv    = (const float*)d_in[7];
    const float* Wr    = (const float*)d_in[8];
    const float* Wo    = (const float*)d_in[9];
    const float* gamma = (const float*)d_in[10];
    const float* beta  = (const float*)d_in[11];
    float* out = (float*)d_out;

    const int ATTN_SMEM = AW * (int)sizeof(float);   // 73472 B
    cudaFuncSetAttribute(attn_mma, cudaFuncAttributeMaxDynamicSharedMemorySize, ATTN_SMEM);

    static float* p_wt = nullptr;
    static float* p_attn = nullptr; static float* p_o = nullptr;
    if (!p_wt) {
        cudaGetSymbolAddress((void**)&p_wt, g_wt);
        cudaGetSymbolAddress((void**)&p_attn, g_attn);
        cudaGetSymbolAddress((void**)&p_o, g_o);
    }
    const size_t WSZ = (size_t)E_DIM * E_DIM;

    transpose5<<<dim3(32, 32, 5), dim3(32, 8)>>>(Wq, Wk, Wv, Wr, Wo);
    gemm_proj<<<dim3(8, 32, 4), 256>>>(w, r);
    ckcr_kernel<<<10240, 256>>>(rwb, rrb);
    attn_mma<<<dim3(16, 16, 4), 256, ATTN_SMEM>>>();
    gemm_wo<<<dim3(8, 32), 256>>>(p_attn, p_wt + 4 * WSZ, p_o);
    addln_kernel<<<4096, 256>>>(w, gamma, beta, out);
}

// round 17
// speedup vs baseline: 1.5115x; 1.5115x over previous
#include <cuda_runtime.h>
#include <cuda_bf16.h>
#include <math.h>
#include <stdint.h>

#define E_DIM 1024
#define QLEN  1024
#define BATCH 4
#define NH    16
#define DH    64

#define SB2 36   // bf16 smem row stride (32 data words + 2 aux + 2 pad)
#define SS 68    // S stride (f32)

// attn smem word offsets
#define OQ2 0        // q2 bf16: 64 x 36
#define OKB 2304     // k bf16: 64 x 36
#define ORP 4608     // rp bf16: 128 x 36
#define OV  9216     // v bf16: 64 x 36 = 2304
#define OS  11520    // S f32: 64 x 68 = 4352
#define OP  15872    // P bf16 packed: 64 x 36 = 2304
#define OM  18176    // m/l/c: 192
#define AW  18368    // total words = 73472 B

// ---------------- scratch (device globals; no allocation allowed) ----------------
__device__ __nv_bfloat16 g_qb[BATCH * NH * QLEN * DH];   // q, bf16
__device__ __nv_bfloat16 g_kb[BATCH * NH * QLEN * DH];   // k/32, bf16
__device__ __nv_bfloat16 g_vb[BATCH * NH * QLEN * DH];   // v, bf16
__device__ __nv_bfloat16 g_rpb[NH * QLEN * DH];          // rp/32, bf16
__device__ uint32_t g_ckb[BATCH * NH * QLEN];            // packed (bf16(ck/32), 0)
__device__ uint32_t g_crb[NH * QLEN];                    // packed (bf16(cr/32), 0)
__device__ float g_attn[BATCH * QLEN * E_DIM];
__device__ float g_o[BATCH * QLEN * E_DIM];
__device__ float g_wt[5 * E_DIM * E_DIM];                // transposed tf32 weights

// ================= helpers =================
__device__ __forceinline__ float tf32r(float x) {
    asm("cvt.rna.tf32.f32 %0, %1;" : "=f"(x) : "f"(x));
    return x;
}
__device__ __forceinline__ uint32_t bf2pack(float e, float o) {
    uint32_t u;
    asm("cvt.rn.bf16x2.f32 %0, %1, %2;" : "=r"(u) : "f"(o), "f"(e));
    return u;
}

#define MMA8(d, a0, a1, a2, a3, b0, b1) \
    asm volatile("mma.sync.aligned.m16n8k8.row.col.f32.tf32.tf32.f32 " \
        "{%0,%1,%2,%3}, {%4,%5,%6,%7}, {%8,%9}, {%0,%1,%2,%3};" \
        : "+f"((d)[0]), "+f"((d)[1]), "+f"((d)[2]), "+f"((d)[3]) \
        : "r"(a0), "r"(a1), "r"(a2), "r"(a3), "r"(b0), "r"(b1))

#define MMA16B(d, a0, a1, a2, a3, b0, b1) \
    asm volatile("mma.sync.aligned.m16n8k16.row.col.f32.bf16.bf16.f32 " \
        "{%0,%1,%2,%3}, {%4,%5,%6,%7}, {%8,%9}, {%0,%1,%2,%3};" \
        : "+f"((d)[0]), "+f"((d)[1]), "+f"((d)[2]), "+f"((d)[3]) \
        : "r"(a0), "r"(a1), "r"(a2), "r"(a3), "r"(b0), "r"(b1))

#define MMA8B(d, a0, a1, b0) \
    asm volatile("mma.sync.aligned.m16n8k8.row.col.f32.bf16.bf16.f32 " \
        "{%0,%1,%2,%3}, {%4,%5}, {%6}, {%0,%1,%2,%3};" \
        : "+f"((d)[0]), "+f"((d)[1]), "+f"((d)[2]), "+f"((d)[3]) \
        : "r"(a0), "r"(a1), "r"(b0))

#define LDSM4T(r0, r1, r2, r3, addr) \
    asm volatile("ldmatrix.sync.aligned.m8n8.x4.trans.shared.b16 {%0,%1,%2,%3}, [%4];" \
        : "=r"(r0), "=r"(r1), "=r"(r2), "=r"(r3) : "r"(addr))

#define CP16(saddr, gptr) \
    asm volatile("cp.async.cg.shared.global [%0], [%1], 16;" :: "r"(saddr), "l"(gptr) : "memory")
#define CP16Z(saddr, gptr, sz) \
    asm volatile("cp.async.cg.shared.global [%0], [%1], 16, %2;" :: "r"(saddr), "l"(gptr), "r"(sz) : "memory")
#define CP4(saddr, gptr) \
    asm volatile("cp.async.ca.shared.global [%0], [%1], 4;" :: "r"(saddr), "l"(gptr) : "memory")
#define CP4Z(saddr, gptr, sz) \
    asm volatile("cp.async.ca.shared.global [%0], [%1], 4, %2;" :: "r"(saddr), "l"(gptr), "r"(sz) : "memory")
#define CPCOMMIT() asm volatile("cp.async.commit_group;" ::: "memory")
#define CPWAIT2()  asm volatile("cp.async.wait_group 2;" ::: "memory")
#define CPWAIT0()  asm volatile("cp.async.wait_group 0;" ::: "memory")

// ---------------- weight transpose + tf32 round: 5 x 1024x1024 ----------------
__global__ void __launch_bounds__(256) transpose5(const float* __restrict__ a0,
                                                  const float* __restrict__ a1,
                                                  const float* __restrict__ a2,
                                                  const float* __restrict__ a3,
                                                  const float* __restrict__ a4)
{
    __shared__ float t[32][33];
    const float* src = (blockIdx.z == 0) ? a0 : (blockIdx.z == 1) ? a1 :
                       (blockIdx.z == 2) ? a2 : (blockIdx.z == 3) ? a3 : a4;
    float* dst = g_wt + (size_t)blockIdx.z * E_DIM * E_DIM;
    int x = blockIdx.x * 32 + threadIdx.x;
    int y0 = blockIdx.y * 32 + threadIdx.y;
#pragma unroll
    for (int j = 0; j < 4; j++)
        t[threadIdx.y + 8 * j][threadIdx.x] = src[(size_t)(y0 + 8 * j) * E_DIM + x];
    __syncthreads();
    int x2 = blockIdx.y * 32 + threadIdx.x;
    int y2 = blockIdx.x * 32 + threadIdx.y;
#pragma unroll
    for (int j = 0; j < 4; j++)
        dst[(size_t)(y2 + 8 * j) * E_DIM + x2] = tf32r(t[threadIdx.x][threadIdx.y + 8 * j]);
}

// ---------------- tf32 GEMM body, cp.async 4-stage (R10-proven core, 128 thr) ----------------
// out modes: 0 bf16 head-major (batch), 2 bf16 head-major (no batch), 3 f32 row-major
__device__ __forceinline__ void gemm_body(const float* __restrict__ A,
                                          const float* __restrict__ Bt,
                                          void* __restrict__ C,
                                          int mode, float scale, int m0, int n0,
                                          uint32_t* sA, uint32_t* sB)
{
    const int tid = threadIdx.x;
    const int wid = tid >> 5, lane = tid & 31;
    const int mw = wid >> 1, nw = wid & 1;
    const int g = lane >> 2, tt = lane & 3;
    const int swz = (g & 6) << 1;
    const int c0w = tt + (0 ^ swz);
    const int c1w = tt + (4 ^ swz);
    const int baseA = (mw * 64 + g) * 16;
    const int baseB = (nw * 64 + g) * 16;

    const int q4 = tid & 3;
    const int row0 = tid >> 2;
    int f_w[4];
#pragma unroll
    for (int l = 0; l < 4; l++) {
        int row = row0 + 32 * l;
        f_w[l] = row * 16 + ((4 * q4) ^ ((row & 6) << 1));
    }

    const float* Ap = A + (size_t)(m0 + row0) * E_DIM + 4 * q4;
    const float* Bp = Bt + (size_t)(n0 + row0) * E_DIM + 4 * q4;
    const uint32_t aBase = (uint32_t)__cvta_generic_to_shared(sA);
    const uint32_t bBase = (uint32_t)__cvta_generic_to_shared(sB);

    float d[4][8][4];
#pragma unroll
    for (int i = 0; i < 4; i++)
#pragma unroll
        for (int j = 0; j < 8; j++)
#pragma unroll
            for (int e = 0; e < 4; e++) d[i][j][e] = 0.f;

#define ISSUE_CHUNK(c, st) do { \
    _Pragma("unroll") \
    for (int l = 0; l < 4; l++) { \
        CP16(aBase + (st) * 8192 + f_w[l] * 4, Ap + (size_t)(32 * l) * E_DIM + (c) * 16); \
        CP16(bBase + (st) * 8192 + f_w[l] * 4, Bp + (size_t)(32 * l) * E_DIM + (c) * 16); \
    } \
    CPCOMMIT(); \
} while (0)

    ISSUE_CHUNK(0, 0);
    ISSUE_CHUNK(1, 1);
    ISSUE_CHUNK(2, 2);

    for (int c = 0; c < 64; c++) {
        const int st = c & 3;
        CPWAIT2();
        __syncthreads();
#pragma unroll
        for (int ks = 0; ks < 2; ks++) {
            const int ko = ks << 3;
            uint32_t af[4][4];
            uint32_t bf2[8][2];
#pragma unroll
            for (int ma = 0; ma < 4; ma++) {
                af[ma][0] = sA[st * 2048 + baseA + ma * 256 +       (c0w ^ ko)];
                af[ma][1] = sA[st * 2048 + baseA + ma * 256 + 128 + (c0w ^ ko)];
                af[ma][2] = sA[st * 2048 + baseA + ma * 256 +       (c1w ^ ko)];
                af[ma][3] = sA[st * 2048 + baseA + ma * 256 + 128 + (c1w ^ ko)];
            }
#pragma unroll
            for (int nb = 0; nb < 8; nb++) {
                bf2[nb][0] = sB[st * 2048 + baseB + nb * 128 + (c0w ^ ko)];
                bf2[nb][1] = sB[st * 2048 + baseB + nb * 128 + (c1w ^ ko)];
            }
#pragma unroll
            for (int ma = 0; ma < 4; ma++)
#pragma unroll
                for (int nb = 0; nb < 8; nb++)
                    MMA8(d[ma][nb], af[ma][0], af[ma][1], af[ma][2], af[ma][3],
                         bf2[nb][0], bf2[nb][1]);
        }
        if (c < 61) ISSUE_CHUNK(c + 3, (c + 3) & 3);
    }
#undef ISSUE_CHUNK

#pragma unroll
    for (int ma = 0; ma < 4; ma++) {
        const int m_base = m0 + mw * 64 + ma * 16 + g;
#pragma unroll
        for (int nb = 0; nb < 8; nb++) {
            const int n = n0 + nw * 64 + nb * 8 + tt * 2;
#pragma unroll
            for (int half = 0; half < 2; half++) {
                const int m = m_base + half * 8;
                float vx = d[ma][nb][half * 2], vy = d[ma][nb][half * 2 + 1];
                if (mode == 0) {
                    int b = m >> 10, i = m & 1023, hh = n >> 6, dd = n & 63;
                    ((uint32_t*)C)[((((size_t)b * NH + hh) * QLEN + i) * DH + dd) >> 1] =
                        bf2pack(vx * scale, vy * scale);
                } else if (mode == 2) {
                    int hh = n >> 6, dd = n & 63;
                    ((uint32_t*)C)[(((size_t)hh * QLEN + m) * DH + dd) >> 1] =
                        bf2pack(vx * scale, vy * scale);
                } else {
                    *(float2*)&((float*)C)[(size_t)m * E_DIM + n] = make_float2(vx, vy);
                }
            }
        }
    }
}

__global__ void __launch_bounds__(128, 2) gemm_proj(const float* __restrict__ w,
                                                    const float* __restrict__ r)
{
    __shared__ uint32_t sA[4][2048];
    __shared__ uint32_t sB[4][2048];
    const int z = blockIdx.z;
    if (z == 3 && blockIdx.y >= 8) return;
    const size_t WSZ = (size_t)E_DIM * E_DIM;
    const float* A = (z == 3) ? r : w;
    const float* Bt = g_wt + (size_t)z * WSZ;
    void* C = (z == 0) ? (void*)g_qb : (z == 1) ? (void*)g_kb :
              (z == 2) ? (void*)g_vb : (void*)g_rpb;
    int mode = (z == 3) ? 2 : 0;
    float scale = (z == 1 || z == 3) ? 0.03125f : 1.0f;
    gemm_body(A, Bt, C, mode, scale, blockIdx.y * 128, blockIdx.x * 128,
              &sA[0][0], &sB[0][0]);
}

__global__ void __launch_bounds__(128, 2) gemm_wo(const float* __restrict__ A,
                                                  const float* __restrict__ Bt,
                                                  float* __restrict__ C)
{
    __shared__ uint32_t sA[4][2048];
    __shared__ uint32_t sB[4][2048];
    gemm_body(A, Bt, C, 3, 1.0f, blockIdx.y * 128, blockIdx.x * 128,
              &sA[0][0], &sB[0][0]);
}

// ---------------- ck/cr from bf16 k/32, rp/32 ----------------
__global__ void __launch_bounds__(256) ckcr_kernel(const float* __restrict__ rwb,
                                                   const float* __restrict__ rrb)
{
    int gw = (blockIdx.x * blockDim.x + threadIdx.x) >> 5;
    int lane = threadIdx.x & 31;
    const int NCK = BATCH * NH * QLEN;
    float s;
    if (gw < NCK) {
        int h = (gw >> 10) & (NH - 1);
        uint32_t u = ((const uint32_t*)g_kb)[(size_t)gw * 32 + lane];
        float lo = __uint_as_float(u << 16);
        float hi = __uint_as_float(u & 0xFFFF0000u);
        s = lo * rwb[h * DH + 2 * lane] + hi * rwb[h * DH + 2 * lane + 1];
    } else {
        int w2 = gw - NCK;
        if (w2 >= NH * QLEN) return;
        int h = w2 >> 10;
        uint32_t u = ((const uint32_t*)g_rpb)[(size_t)w2 * 32 + lane];
        float lo = __uint_as_float(u << 16);
        float hi = __uint_as_float(u & 0xFFFF0000u);
        s = lo * rrb[h * DH + 2 * lane] + hi * rrb[h * DH + 2 * lane + 1];
    }
#pragma unroll
    for (int off = 16; off; off >>= 1) s += __shfl_down_sync(0xffffffffu, s, off);
    if (lane == 0) {
        if (gw < NCK) g_ckb[gw] = bf2pack(s, 0.f);
        else g_crb[gw - NCK] = bf2pack(s, 0.f);
    }
}

// ---------------- fused attention: full-bf16 MMAs, windowed P, rolling rp, cp.async ----------------
__global__ void __launch_bounds__(256, 3) attn_mma()
{
    extern __shared__ float sm[];
    uint32_t* smu = (uint32_t*)sm;
    float* S_s = sm + OS;
    float* m_s = sm + OM;
    float* l_s = sm + OM + 64;
    float* c_s = sm + OM + 128;

    const int tid = threadIdx.x;
    const int wid = tid >> 5, lane = tid & 31;
    const int g = lane >> 2, tg = lane & 3;
    const int qt = 15 - blockIdx.x;
    const int h = blockIdx.y, b = blockIdx.z;
    const int i0 = qt * 64;
    const size_t headelem = ((size_t)b * NH + h) * QLEN * DH;
    const char* qb_p  = (const char*)g_qb  + (headelem + (size_t)i0 * DH) * 2;
    const char* kb_p  = (const char*)g_kb  + headelem * 2;
    const char* vb_p  = (const char*)g_vb  + headelem * 2;
    const char* rp_p  = (const char*)g_rpb + (size_t)h * QLEN * DH * 2;
    const uint32_t* ckb_p = g_ckb + ((size_t)b * NH + h) * QLEN;
    const uint32_t* crb_p = g_crb + (size_t)h * QLEN;

    const int mt = wid >> 1;
    const int nt = wid & 1;
    const int u0 = 48 - 16 * mt;
    const int pcol0 = u0 + nt * 40;

    const uint32_t q2S = (uint32_t)__cvta_generic_to_shared(smu + OQ2);
    const uint32_t kS  = (uint32_t)__cvta_generic_to_shared(smu + OKB);
    const uint32_t rpS = (uint32_t)__cvta_generic_to_shared(smu + ORP);
    const uint32_t vS  = (uint32_t)__cvta_generic_to_shared(smu + OV);

    // ---- static init: aux/pad words ----
    if (tid < 64) {
        int ba = OQ2 + tid * SB2;
        smu[ba + 32] = 0x00003F80u;  // (bf16 1.0, 0) -> A' aux = [1,0,...]
        smu[ba + 33] = 0; smu[ba + 34] = 0; smu[ba + 35] = 0;
        ba = OKB + tid * SB2;
        smu[ba + 33] = 0; smu[ba + 34] = 0; smu[ba + 35] = 0;
        m_s[tid] = -INFINITY; l_s[tid] = 0.f;
    }
    if (tid < 128) {
        int ba = ORP + tid * SB2;
        smu[ba + 33] = 0; smu[ba + 34] = 0; smu[ba + 35] = 0;
    }

    // ---- prologue fills (q2 + kt=0 k/v/rp/aux) ----
    {
        const int m_base0 = 960 - i0;
#pragma unroll
        for (int it = 0; it < 2; it++) {   // q2 + k + v: 64 rows x 8 granules each
            int idx = tid + 256 * it;
            int row = idx >> 3, j = idx & 7;
            CP16(q2S + (uint32_t)(row * SB2 + 4 * j) * 4, qb_p + (size_t)row * 128 + 16 * j);
            CP16(kS  + (uint32_t)(row * SB2 + 4 * j) * 4, kb_p + (size_t)row * 128 + 16 * j);
            CP16(vS  + (uint32_t)(row * SB2 + 4 * j) * 4, vb_p + (size_t)row * 128 + 16 * j);
        }
#pragma unroll
        for (int it = 0; it < 4; it++) {   // rp: 128 rows x 8 granules
            int idx = tid + 256 * it;
            int row = idx >> 3, j = idx & 7;
            int mg = m_base0 + row;
            int slot = mg & 127;
            uint32_t sz = (mg < QLEN) ? 16u : 0u;
            int mgc = (mg < QLEN) ? mg : (QLEN - 1);
            CP16Z(rpS + (uint32_t)(slot * SB2 + 4 * j) * 4, rp_p + (size_t)mgc * 128 + 16 * j, sz);
        }
        if (tid < 64) {
            CP4(kS + (uint32_t)(tid * SB2 + 32) * 4, ckb_p + tid);
        } else if (tid < 192) {
            int row = tid - 64;
            int mg = m_base0 + row;
            int slot = mg & 127;
            uint32_t sz = (mg < QLEN) ? 4u : 0u;
            int mgc = (mg < QLEN) ? mg : (QLEN - 1);
            CP4Z(rpS + (uint32_t)(slot * SB2 + 32) * 4, crb_p + mgc, sz);
        }
        CPCOMMIT();
    }

    float acc_o[4][4];
#pragma unroll
    for (int na = 0; na < 4; na++)
#pragma unroll
        for (int e = 0; e < 4; e++) acc_o[na][e] = 0.f;

    const int aR0 = OQ2 + (mt * 16 + g) * SB2;
    const int aR1 = aR0 + 8 * SB2;
    const int aP0 = OP + (mt * 16 + g) * SB2;
    const int aP1 = aP0 + 8 * SB2;
    // ldmatrix base for V (per-lane): matrix row j = lane&15, col half = (lane>>4)*8
    const uint32_t vmBase = vS +
        (uint32_t)(((lane & 15) * SB2 + ((nt * 32 + ((lane >> 4) << 3)) >> 1)) * 4);

    for (int kt = 0; kt <= qt; kt++) {
        const int j0 = kt * 64;
        const int m_base = 960 - i0 + j0;
        const int mb7 = m_base & 127;

        CPWAIT0();
        __syncthreads();

        int kb[4], pb[5];
#pragma unroll
        for (int na = 0; na < 4; na++) kb[na] = OKB + (nt * 32 + na * 8 + g) * SB2;
#pragma unroll
        for (int na = 0; na < 5; na++)
            pb[na] = ORP + ((mb7 + pcol0 + na * 8 + g) & 127) * SB2;

        // ---- S-phase: bf16 k16 MMAs ----
        float sc[4][4], pc[5][4];
#pragma unroll
        for (int na = 0; na < 4; na++)
#pragma unroll
            for (int e = 0; e < 4; e++) sc[na][e] = 0.f;
#pragma unroll
        for (int na = 0; na < 5; na++)
#pragma unroll
            for (int e = 0; e < 4; e++) pc[na][e] = 0.f;
#pragma unroll
        for (int s = 0; s < 4; s++) {
            uint32_t a0 = smu[aR0 + 8 * s + tg];
            uint32_t a1 = smu[aR1 + 8 * s + tg];
            uint32_t a2 = smu[aR0 + 8 * s + 4 + tg];
            uint32_t a3 = smu[aR1 + 8 * s + 4 + tg];
#pragma unroll
            for (int na = 0; na < 4; na++)
                MMA16B(sc[na], a0, a1, a2, a3,
                       smu[kb[na] + 8 * s + tg], smu[kb[na] + 8 * s + 4 + tg]);
#pragma unroll
            for (int na = 0; na < 5; na++)
                MMA16B(pc[na], a0, a1, a2, a3,
                       smu[pb[na] + 8 * s + tg], smu[pb[na] + 8 * s + 4 + tg]);
        }
        {   // aux k8 (bias via [1] column)
            uint32_t a0 = smu[aR0 + 32 + tg];
            uint32_t a1 = smu[aR1 + 32 + tg];
#pragma unroll
            for (int na = 0; na < 4; na++)
                MMA8B(sc[na], a0, a1, smu[kb[na] + 32 + tg]);
#pragma unroll
            for (int na = 0; na < 5; na++)
                MMA8B(pc[na], a0, a1, smu[pb[na] + 32 + tg]);
        }
        // scatter P window (assign into S band)
#pragma unroll
        for (int na = 0; na < 5; na++) {
            int ub = pcol0 + na * 8 + 2 * tg;
#pragma unroll
            for (int e = 0; e < 4; e++) {
                int il = mt * 16 + g + (e >> 1) * 8;
                int jl = ub + (e & 1) - 63 + il;
                if (jl >= 0 && jl < 64) S_s[il * SS + jl] = pc[na][e];
            }
        }
        __syncthreads();

        // ---- early issue of k/rp/aux for kt+1 ----
        if (kt < qt) {
            const int j1 = j0 + 64;
            const int mb1 = m_base + 64;
#pragma unroll
            for (int it = 0; it < 2; it++) {   // k: 64 rows x 8 granules
                int idx = tid + 256 * it;
                int row = idx >> 3, j = idx & 7;
                CP16(kS + (uint32_t)(row * SB2 + 4 * j) * 4,
                     kb_p + (size_t)(j1 + row) * 128 + 16 * j);
            }
#pragma unroll
            for (int it = 0; it < 2; it++) {   // rp top 64 rows x 8 granules
                int idx = tid + 256 * it;
                int row = 64 + (idx >> 3), j = idx & 7;
                int mg = mb1 + row;
                int slot = mg & 127;
                uint32_t sz = (mg < QLEN) ? 16u : 0u;
                int mgc = (mg < QLEN) ? mg : (QLEN - 1);
                CP16Z(rpS + (uint32_t)(slot * SB2 + 4 * j) * 4,
                      rp_p + (size_t)mgc * 128 + 16 * j, sz);
            }
            if (tid < 64) {
                CP4(kS + (uint32_t)(tid * SB2 + 32) * 4, ckb_p + j1 + tid);
            } else if (tid < 128) {
                int row = tid;   // 64..127
                int mg = mb1 + row;
                int slot = mg & 127;
                uint32_t sz = (mg < QLEN) ? 4u : 0u;
                int mgc = (mg < QLEN) ? mg : (QLEN - 1);
                CP4Z(rpS + (uint32_t)(slot * SB2 + 32) * 4, crb_p + mgc, sz);
            }
        }

        // ---- S1 accumulate into S (float2 RMW) ----
#pragma unroll
        for (int na = 0; na < 4; na++) {
            int cb = nt * 32 + na * 8 + 2 * tg;
            int il0 = mt * 16 + g;
            float2 x0 = *(float2*)&S_s[il0 * SS + cb];
            x0.x += sc[na][0]; x0.y += sc[na][1];
            *(float2*)&S_s[il0 * SS + cb] = x0;
            float2 x1 = *(float2*)&S_s[(il0 + 8) * SS + cb];
            x1.x += sc[na][2]; x1.y += sc[na][3];
            *(float2*)&S_s[(il0 + 8) * SS + cb] = x1;
        }
        __syncthreads();

        // ---- online softmax: reads f32 S, writes packed bf16 P ----
        {
            int row = tid >> 2, p = tid & 3;
            int c0 = p * 16;
            bool diag = (kt == qt);
            float mo = m_s[row];
            float mx = mo;
            float4 vv[4];
#pragma unroll
            for (int jv = 0; jv < 4; jv++) {
                vv[jv] = *(const float4*)&S_s[row * SS + c0 + jv * 4];
                if (diag) {
                    int base = c0 + jv * 4;
                    if (base + 0 > row) vv[jv].x = -1e30f;
                    if (base + 1 > row) vv[jv].y = -1e30f;
                    if (base + 2 > row) vv[jv].z = -1e30f;
                    if (base + 3 > row) vv[jv].w = -1e30f;
                }
                mx = fmaxf(mx, fmaxf(fmaxf(vv[jv].x, vv[jv].y), fmaxf(vv[jv].z, vv[jv].w)));
            }
            mx = fmaxf(mx, __shfl_xor_sync(0xffffffffu, mx, 1));
            mx = fmaxf(mx, __shfl_xor_sync(0xffffffffu, mx, 2));
            float corr = __expf(mo - mx);
            float sum = 0.f;
            int pr = OP + row * SB2 + p * 8;
#pragma unroll
            for (int jv = 0; jv < 4; jv++) {
                float4 pv;
                pv.x = __expf(vv[jv].x - mx);
                pv.y = __expf(vv[jv].y - mx);
                pv.z = __expf(vv[jv].z - mx);
                pv.w = __expf(vv[jv].w - mx);
                sum += (pv.x + pv.y) + (pv.z + pv.w);
                uint2 u;
                u.x = bf2pack(pv.x, pv.y);
                u.y = bf2pack(pv.z, pv.w);
                *(uint2*)&smu[pr + 2 * jv] = u;
            }
            sum += __shfl_xor_sync(0xffffffffu, sum, 1);
            sum += __shfl_xor_sync(0xffffffffu, sum, 2);
            if (p == 0) {
                m_s[row] = mx;
                l_s[row] = l_s[row] * corr + sum;
                c_s[row] = corr;
            }
        }
        __syncthreads();

        // ---- PV (bf16, ldmatrix.trans for V) ----
        {
            float cr0 = c_s[mt * 16 + g], cr1 = c_s[mt * 16 + 8 + g];
#pragma unroll
            for (int na = 0; na < 4; na++) {
                acc_o[na][0] *= cr0; acc_o[na][1] *= cr0;
                acc_o[na][2] *= cr1; acc_o[na][3] *= cr1;
            }
#pragma unroll
            for (int ks = 0; ks < 4; ks++) {
                uint32_t a0 = smu[aP0 + 8 * ks + tg];
                uint32_t a1 = smu[aP1 + 8 * ks + tg];
                uint32_t a2 = smu[aP0 + 8 * ks + 4 + tg];
                uint32_t a3 = smu[aP1 + 8 * ks + 4 + tg];
#pragma unroll
                for (int nb16 = 0; nb16 < 2; nb16++) {
                    uint32_t r0, r1, r2, r3;
                    LDSM4T(r0, r1, r2, r3,
                           vmBase + (uint32_t)((16 * ks * SB2 + 8 * nb16) * 4));
                    MMA16B(acc_o[2 * nb16 + 0], a0, a1, a2, a3, r0, r1);
                    MMA16B(acc_o[2 * nb16 + 1], a0, a1, a2, a3, r2, r3);
                }
            }
        }
        __syncthreads();

        // ---- early issue of v for kt+1, then commit ----
        if (kt < qt) {
            const int j1 = j0 + 64;
#pragma unroll
            for (int it = 0; it < 2; it++) {
                int idx = tid + 256 * it;
                int row = idx >> 3, j = idx & 7;
                CP16(vS + (uint32_t)(row * SB2 + 4 * j) * 4,
                     vb_p + (size_t)(j1 + row) * 128 + 16 * j);
            }
        }
        CPCOMMIT();
    }

    // ---- write out (token-major for Wo GEMM) ----
    {
        int il0 = mt * 16 + g;
        float inv0 = 1.f / l_s[il0], inv1 = 1.f / l_s[il0 + 8];
#pragma unroll
        for (int na = 0; na < 4; na++) {
            int d0 = h * DH + nt * 32 + na * 8 + 2 * tg;
            size_t o0 = ((size_t)b * QLEN + i0 + il0) * E_DIM + d0;
            size_t o1 = ((size_t)b * QLEN + i0 + il0 + 8) * E_DIM + d0;
            *(float2*)&g_attn[o0] = make_float2(acc_o[na][0] * inv0, acc_o[na][1] * inv0);
            *(float2*)&g_attn[o1] = make_float2(acc_o[na][2] * inv1, acc_o[na][3] * inv1);
        }
    }
}

// ---------------- residual + layernorm (float4) ----------------
__global__ void __launch_bounds__(256) addln_kernel(const float* __restrict__ w,
                                                    const float* __restrict__ gamma,
                                                    const float* __restrict__ beta,
                                                    float* __restrict__ out)
{
    __shared__ float xs[E_DIM];
    __shared__ float red[64];
    int row = blockIdx.x;
    size_t base = (size_t)row * E_DIM;
    int j = threadIdx.x * 4;
    float4 a = *(const float4*)&w[base + j];
    float4 o = *(const float4*)&g_o[base + j];
    float4 x = make_float4(a.x + o.x, a.y + o.y, a.z + o.z, a.w + o.w);
    *(float4*)&xs[j] = x;
    float s = (x.x + x.y) + (x.z + x.w);
    float s2 = (x.x * x.x + x.y * x.y) + (x.z * x.z + x.w * x.w);
#pragma unroll
    for (int off = 16; off; off >>= 1) {
        s  += __shfl_down_sync(0xffffffffu, s, off);
        s2 += __shfl_down_sync(0xffffffffu, s2, off);
    }
    int wid = threadIdx.x >> 5, lane = threadIdx.x & 31;
    if (lane == 0) { red[wid] = s; red[32 + wid] = s2; }
    __syncthreads();
    if (threadIdx.x == 0) {
        float S = 0.f, S2 = 0.f;
        for (int i = 0; i < 8; i++) { S += red[i]; S2 += red[32 + i]; }
        red[0] = S; red[1] = S2;
    }
    __syncthreads();
    float mean = red[0] * (1.f / E_DIM);
    float var = red[1] * (1.f / E_DIM) - mean * mean;
    float inv = rsqrtf(var + 1e-3f);
    float4 gm = *(const float4*)&gamma[j];
    float4 bt = *(const float4*)&beta[j];
    float4 xv = *(const float4*)&xs[j];
    float4 rr;
    rr.x = (xv.x - mean) * inv * gm.x + bt.x;
    rr.y = (xv.y - mean) * inv * gm.y + bt.y;
    rr.z = (xv.z - mean) * inv * gm.z + bt.z;
    rr.w = (xv.w - mean) * inv * gm.w + bt.w;
    *(float4*)&out[base + j] = rr;
}

// ---------------- launch ----------------
extern "C" void kernel_launch(void* const* d_in, const int* in_sizes, int n_in,
                              void* d_out, int out_size)
{
    const float* w     = (const float*)d_in[0];
    const float* r     = (const float*)d_in[1];
    const float* rwb   = (const float*)d_in[2];
    const float* rrb   = (const float*)d_in[3];
    // d_in[4] attn_mask: strictly-causal, computed analytically
    const float* Wq    = (const float*)d_in[5];
    const float* Wk    = (const float*)d_in[6];
    const float* Wv    = (const float*)d_in[7];
    const float* Wr    = (const float*)d_in[8];
    const float* Wo    = (const float*)d_in[9];
    const float* gamma = (const float*)d_in[10];
    const float* beta  = (const float*)d_in[11];
    float* out = (float*)d_out;

    const int ATTN_SMEM = AW * (int)sizeof(float);   // 73472 B
    cudaFuncSetAttribute(attn_mma, cudaFuncAttributeMaxDynamicSharedMemorySize, ATTN_SMEM);

    static float* p_wt = nullptr;
    static float* p_attn = nullptr; static float* p_o = nullptr;
    if (!p_wt) {
        cudaGetSymbolAddress((void**)&p_wt, g_wt);
        cudaGetSymbolAddress((void**)&p_attn, g_attn);
        cudaGetSymbolAddress((void**)&p_o, g_o);
    }
    const size_t WSZ = (size_t)E_DIM * E_DIM;

    transpose5<<<dim3(32, 32, 5), dim3(32, 8)>>>(Wq, Wk, Wv, Wr, Wo);
    gemm_proj<<<dim3(8, 32, 4), 128>>>(w, r);
    ckcr_kernel<<<10240, 256>>>(rwb, rrb);
    attn_mma<<<dim3(16, 16, 4), 256, ATTN_SMEM>>>();
    gemm_wo<<<dim3(8, 32), 128>>>(p_attn, p_wt + 4 * WSZ, p_o);
    addln_kernel<<<4096, 256>>>(w, gamma, beta, out);
}